// round 12
// baseline (speedup 1.0000x reference)
#include <cuda_runtime.h>

// TensorProductLayer, warp-autonomous double-buffered: each warp owns 64
// consecutive pairs as two 32-pair slices with separate cp.async groups.
// Stage A, stage B, wait(1) -> compute+store A (B still in flight),
// wait(0) -> compute+store B. No block barriers; warps free-run.
//  - stage: cp.async.cg 16B (208 f4/slice, 7 predicated passes)
//  - compute: 1 pair/lane from warp smem (strides 3,9 coprime to 32)
//  - results overwrite the slice; cooperative per-warp STG.128 (104 f4)
// Per pair: a=x0, b=y0, u=x1(3), v=y1(3), A=x2(9), B=y2(9)
//   out0      = a*b + u.v + <A,B>_F
//   out1[i]   = a*v[i] + b*u[i] + (u^T B)[i] + (A v)[i]
//   out2[i,j] = a*B[i,j] + b*A[i,j] + u[i]*v[j] + (A B)[i,j]

#define TPB 256          // 8 warps per block
#define SLICE_F4 208     // f4 per 32-pair slice
// slice f4 offsets:    sa 0, sb 8,  su 16,  sv 40,  A 64,  B 136
// slice float offsets: sa 0, sb 32, su 64, sv 160, A 256, B 544

__device__ __forceinline__ void cp16(float4* smem_dst, const float4* gmem_src)
{
    unsigned saddr = (unsigned)__cvta_generic_to_shared(smem_dst);
    asm volatile("cp.async.cg.shared.global [%0], [%1], 16;"
                 :: "r"(saddr), "l"(gmem_src));
}

__device__ __forceinline__ void tp_pair(
    float a, float b,
    const float* __restrict__ u, const float* __restrict__ v,
    const float* __restrict__ A, const float* __restrict__ B,
    float* __restrict__ r0, float* __restrict__ r1, float* __restrict__ r2)
{
    float s0 = a * b;
#pragma unroll
    for (int i = 0; i < 3; ++i) s0 = fmaf(u[i], v[i], s0);
#pragma unroll
    for (int i = 0; i < 9; ++i) s0 = fmaf(A[i], B[i], s0);
    *r0 = s0;

#pragma unroll
    for (int i = 0; i < 3; ++i) {
        float t = a * v[i];
        t = fmaf(b, u[i], t);
#pragma unroll
        for (int d = 0; d < 3; ++d) t = fmaf(u[d], B[d * 3 + i], t);
#pragma unroll
        for (int e = 0; e < 3; ++e) t = fmaf(A[i * 3 + e], v[e], t);
        r1[i] = t;
    }

#pragma unroll
    for (int i = 0; i < 3; ++i) {
#pragma unroll
        for (int j = 0; j < 3; ++j) {
            float t = a * B[i * 3 + j];
            t = fmaf(b, A[i * 3 + j], t);
            t = fmaf(u[i], v[j], t);
#pragma unroll
            for (int e = 0; e < 3; ++e) t = fmaf(A[i * 3 + e], B[e * 3 + j], t);
            r2[i * 3 + j] = t;
        }
    }
}

// Stage one 32-pair slice (208 f4) into wb; g = f4 index of slice start.
__device__ __forceinline__ void stage_slice(
    float4* wb, int g, int lane,
    const float4* __restrict__ x0, const float4* __restrict__ y0,
    const float4* __restrict__ x1, const float4* __restrict__ y1,
    const float4* __restrict__ x2, const float4* __restrict__ y2)
{
    const int g3 = g * 3, g9 = g * 9;
#pragma unroll
    for (int k = 0; k < 7; ++k) {
        int i = lane + 32 * k;
        if (i < SLICE_F4) {
            const float4* src;
            if (i < 8)        src = x0 + (g  + i);
            else if (i < 16)  src = y0 + (g  + i - 8);
            else if (i < 40)  src = x1 + (g3 + i - 16);
            else if (i < 64)  src = y1 + (g3 + i - 40);
            else if (i < 136) src = x2 + (g9 + i - 64);
            else              src = y2 + (g9 + i - 136);
            cp16(wb + i, src);
        }
    }
}

// Compute 32 pairs in place (lane = pair), then cooperative store (104 f4).
__device__ __forceinline__ void compute_store_slice(
    float4* wb, int g, int lane,
    float4* __restrict__ o0, float4* __restrict__ o1, float4* __restrict__ o2)
{
    __syncwarp();
    {
        float* f = reinterpret_cast<float*>(wb);
        float a = f[lane], b = f[32 + lane];
        float u[3], v[3], A[9], B[9];
#pragma unroll
        for (int i = 0; i < 3; ++i) { u[i] = f[64 + lane * 3 + i]; v[i] = f[160 + lane * 3 + i]; }
#pragma unroll
        for (int i = 0; i < 9; ++i) { A[i] = f[256 + lane * 9 + i]; B[i] = f[544 + lane * 9 + i]; }

        float r0, r1[3], r2[9];
        tp_pair(a, b, u, v, A, B, &r0, r1, r2);

        f[lane] = r0;
#pragma unroll
        for (int i = 0; i < 3; ++i) f[64 + lane * 3 + i] = r1[i];
#pragma unroll
        for (int i = 0; i < 9; ++i) f[256 + lane * 9 + i] = r2[i];
    }
    __syncwarp();

    const int g3 = g * 3, g9 = g * 9;
#pragma unroll
    for (int k = 0; k < 4; ++k) {
        int i = lane + 32 * k;
        if (i < 104) {
            if (i < 8)       __stcs(o0 + (g  + i),      wb[i]);
            else if (i < 32) __stcs(o1 + (g3 + i - 8),  wb[16 + (i - 8)]);
            else             __stcs(o2 + (g9 + i - 32), wb[64 + (i - 32)]);
        }
    }
}

__global__ void __launch_bounds__(TPB)
tp_kernel_wdb(const float* __restrict__ x0f, const float* __restrict__ y0f,
              const float* __restrict__ x1f, const float* __restrict__ y1f,
              const float* __restrict__ x2f, const float* __restrict__ y2f,
              float* __restrict__ o0f, float* __restrict__ o1f, float* __restrict__ o2f,
              int total)
{
    __shared__ float4 sbuf[8 * 2 * SLICE_F4];   // 53,248 B -> 4 CTAs/SM

    const int tid  = threadIdx.x;
    const int lane = tid & 31;
    const int warp = tid >> 5;
    const int pair0 = blockIdx.x * (TPB * 2) + warp * 64;  // warp owns 64 pairs

    float4* wbA = sbuf + warp * (2 * SLICE_F4);
    float4* wbB = wbA + SLICE_F4;

    const float4* x0 = reinterpret_cast<const float4*>(x0f);
    const float4* y0 = reinterpret_cast<const float4*>(y0f);
    const float4* x1 = reinterpret_cast<const float4*>(x1f);
    const float4* y1 = reinterpret_cast<const float4*>(y1f);
    const float4* x2 = reinterpret_cast<const float4*>(x2f);
    const float4* y2 = reinterpret_cast<const float4*>(y2f);
    float4* o0 = reinterpret_cast<float4*>(o0f);
    float4* o1 = reinterpret_cast<float4*>(o1f);
    float4* o2 = reinterpret_cast<float4*>(o2f);

    if (pair0 + 64 <= total) {
        // ================= fast path =================
        const int gA = pair0 >> 2;        // f4 index of slice A
        const int gB = gA + 8;            // slice B starts 32 pairs later

        stage_slice(wbA, gA, lane, x0, y0, x1, y1, x2, y2);
        asm volatile("cp.async.commit_group;");
        stage_slice(wbB, gB, lane, x0, y0, x1, y1, x2, y2);
        asm volatile("cp.async.commit_group;");

        asm volatile("cp.async.wait_group 1;");   // A ready; B still in flight
        compute_store_slice(wbA, gA, lane, o0, o1, o2);

        asm volatile("cp.async.wait_group 0;");   // B ready
        compute_store_slice(wbB, gB, lane, o0, o1, o2);
    } else {
        // ================= tail path: scalar with guards =================
#pragma unroll
        for (int h = 0; h < 2; ++h) {
            int p = pair0 + h * 32 + lane;
            if (p < total) {
                float a = x0f[p], b = y0f[p];
                float u[3], v[3], A[9], B[9];
#pragma unroll
                for (int i = 0; i < 3; ++i) { u[i] = x1f[p * 3 + i]; v[i] = y1f[p * 3 + i]; }
#pragma unroll
                for (int i = 0; i < 9; ++i) { A[i] = x2f[p * 9 + i]; B[i] = y2f[p * 9 + i]; }
                float r0, r1[3], r2[9];
                tp_pair(a, b, u, v, A, B, &r0, r1, r2);
                o0f[p] = r0;
#pragma unroll
                for (int i = 0; i < 3; ++i) o1f[p * 3 + i] = r1[i];
#pragma unroll
                for (int i = 0; i < 9; ++i) o2f[p * 9 + i] = r2[i];
            }
        }
    }
}

extern "C" void kernel_launch(void* const* d_in, const int* in_sizes, int n_in,
                              void* d_out, int out_size)
{
    // Resolve inputs by element count: s = base (rank-0), 3s (rank-1), 9s (rank-2).
    // First occurrence of a size = x tensor, second = y tensor (robust to both
    // metadata orderings).
    int s = in_sizes[0];
    for (int i = 1; i < n_in; ++i) if (in_sizes[i] < s) s = in_sizes[i];

    const float* X[3] = {nullptr, nullptr, nullptr};
    const float* Y[3] = {nullptr, nullptr, nullptr};
    for (int i = 0; i < n_in; ++i) {
        int r;
        if (in_sizes[i] == s)          r = 0;
        else if (in_sizes[i] == 3 * s) r = 1;
        else                           r = 2;
        if (X[r] == nullptr) X[r] = (const float*)d_in[i];
        else                 Y[r] = (const float*)d_in[i];
    }

    float* o0 = (float*)d_out;       // s elements
    float* o1 = o0 + (size_t)s;      // 3s elements
    float* o2 = o0 + (size_t)4 * s;  // 9s elements

    int blocks = (s + 2 * TPB - 1) / (2 * TPB);   // 512 pairs per block
    tp_kernel_wdb<<<blocks, TPB>>>(X[0], Y[0], X[1], Y[1], X[2], Y[2],
                                   o0, o1, o2, s);
}

// round 13
// speedup vs baseline: 1.0058x; 1.0058x over previous
#include <cuda_runtime.h>

// TensorProductLayer, smem-staged, split-tile cp.async pipeline (straight-line):
//  - block = 256 pairs as two 128-pair half-tiles, each its own cp.async group
//  - compute+store of half 0 overlaps arrival of half 1 (wait_group 1 -> 0)
//  - per-thread scalar compute from smem (strides 1,3,9 coprime to 32)
//  - cooperative STG.128 stores; all indexing 32-bit
//
// FINAL: four independent structures (bulk-sync, split-tile, warp-autonomous,
// warp double-buffered) all measure DRAM ~90% / ~273us ncu with exact-minimal
// 1.95 GB traffic -> HBM read/write turnaround floor. This variant is the
// best-measured of the set.
//
// Per pair: a=x0, b=y0, u=x1(3), v=y1(3), A=x2(9), B=y2(9)
//   out0      = a*b + u.v + <A,B>_F
//   out1[i]   = a*v[i] + b*u[i] + (u^T B)[i] + (A v)[i]
//   out2[i,j] = a*B[i,j] + b*A[i,j] + u[i]*v[j] + (A B)[i,j]

#define TPB 256      // threads per block
#define PT  128      // pairs per half-tile
#define BUF_F4 832   // f4 per half-tile buffer
// per-buffer f4 offsets:    sa 0, sb 32, su 64, sv 160, sA 256, sB 544
// per-buffer float offsets: sa 0, sb 128, su 256, sv 640, sA 1024, sB 2176

__device__ __forceinline__ void cp16(float4* smem_dst, const float4* gmem_src)
{
    unsigned saddr = (unsigned)__cvta_generic_to_shared(smem_dst);
    asm volatile("cp.async.cg.shared.global [%0], [%1], 16;"
                 :: "r"(saddr), "l"(gmem_src));
}

__device__ __forceinline__ void tp_pair(
    float a, float b,
    const float* __restrict__ u, const float* __restrict__ v,
    const float* __restrict__ A, const float* __restrict__ B,
    float* __restrict__ r0, float* __restrict__ r1, float* __restrict__ r2)
{
    float s0 = a * b;
#pragma unroll
    for (int i = 0; i < 3; ++i) s0 = fmaf(u[i], v[i], s0);
#pragma unroll
    for (int i = 0; i < 9; ++i) s0 = fmaf(A[i], B[i], s0);
    *r0 = s0;

#pragma unroll
    for (int i = 0; i < 3; ++i) {
        float t = a * v[i];
        t = fmaf(b, u[i], t);
#pragma unroll
        for (int d = 0; d < 3; ++d) t = fmaf(u[d], B[d * 3 + i], t);
#pragma unroll
        for (int e = 0; e < 3; ++e) t = fmaf(A[i * 3 + e], v[e], t);
        r1[i] = t;
    }

#pragma unroll
    for (int i = 0; i < 3; ++i) {
#pragma unroll
        for (int j = 0; j < 3; ++j) {
            float t = a * B[i * 3 + j];
            t = fmaf(b, A[i * 3 + j], t);
            t = fmaf(u[i], v[j], t);
#pragma unroll
            for (int e = 0; e < 3; ++e) t = fmaf(A[i * 3 + e], B[e * 3 + j], t);
            r2[i * 3 + j] = t;
        }
    }
}

// Stage one 128-pair half-tile (832 f4) into buf over 256 threads.
// g = f4 index of half-tile start in rank-0 space (all fits in 32-bit).
__device__ __forceinline__ void stage_half(
    float4* buf, int g, int tid,
    const float4* __restrict__ x0, const float4* __restrict__ y0,
    const float4* __restrict__ x1, const float4* __restrict__ y1,
    const float4* __restrict__ x2, const float4* __restrict__ y2)
{
    const int g3 = g * 3, g9 = g * 9;
    // pass 0: sa(32) | sb(32) | su(96) | sv(96)
    {
        const float4* src;
        if (tid < 32)        src = x0 + (g + tid);
        else if (tid < 64)   src = y0 + (g + tid - 32);
        else if (tid < 160)  src = x1 + (g3 + tid - 64);
        else                 src = y1 + (g3 + tid - 160);
        cp16(buf + tid, src);
    }
    // pass 1: sA f4 0..255
    cp16(buf + 256 + tid, x2 + (g9 + tid));
    // pass 2: sA f4 256..287 (32) then sB f4 0..223 (224)
    if (tid < 32) cp16(buf + 512 + tid, x2 + (g9 + 256 + tid));
    else          cp16(buf + 512 + tid, y2 + (g9 + tid - 32));
    // pass 3: sB f4 224..287 (64)
    if (tid < 64) cp16(buf + 768 + tid, y2 + (g9 + 224 + tid));
}

// Compute 128 pairs in place (threads 0..127 only).
__device__ __forceinline__ void compute_half(float4* buf, int tid)
{
    if (tid < PT) {
        float* f = reinterpret_cast<float*>(buf);
        float a = f[tid], b = f[128 + tid];
        float u[3], v[3], A[9], B[9];
#pragma unroll
        for (int i = 0; i < 3; ++i) { u[i] = f[256 + tid * 3 + i]; v[i] = f[640 + tid * 3 + i]; }
#pragma unroll
        for (int i = 0; i < 9; ++i) { A[i] = f[1024 + tid * 9 + i]; B[i] = f[2176 + tid * 9 + i]; }

        float r0, r1[3], r2[9];
        tp_pair(a, b, u, v, A, B, &r0, r1, r2);

        f[tid] = r0;
#pragma unroll
        for (int i = 0; i < 3; ++i) f[256 + tid * 3 + i] = r1[i];
#pragma unroll
        for (int i = 0; i < 9; ++i) f[1024 + tid * 9 + i] = r2[i];
    }
}

// Store results of one half-tile (416 f4) over 256 threads.
__device__ __forceinline__ void store_half(
    const float4* buf, int g, int tid,
    float4* __restrict__ o0, float4* __restrict__ o1, float4* __restrict__ o2)
{
    const int g3 = g * 3, g9 = g * 9;
    if (tid < 32)
        __stcs(o0 + (g + tid), buf[tid]);
    else if (tid < 128)
        __stcs(o1 + (g3 + tid - 32), buf[64 + (tid - 32)]);
    else
        __stcs(o2 + (g9 + tid - 128), buf[256 + (tid - 128)]);
    if (tid < 160)
        __stcs(o2 + (g9 + 128 + tid), buf[384 + tid]);
}

__global__ void __launch_bounds__(TPB)
tp_kernel_split(const float* __restrict__ x0f, const float* __restrict__ y0f,
                const float* __restrict__ x1f, const float* __restrict__ y1f,
                const float* __restrict__ x2f, const float* __restrict__ y2f,
                float* __restrict__ o0f, float* __restrict__ o1f, float* __restrict__ o2f,
                int total)
{
    __shared__ float4 sbuf[2 * BUF_F4];   // 26,624 B -> 8 CTAs/SM

    const int tid = threadIdx.x;
    const int P0 = blockIdx.x * (2 * PT);

    const float4* x0 = reinterpret_cast<const float4*>(x0f);
    const float4* y0 = reinterpret_cast<const float4*>(y0f);
    const float4* x1 = reinterpret_cast<const float4*>(x1f);
    const float4* y1 = reinterpret_cast<const float4*>(y1f);
    const float4* x2 = reinterpret_cast<const float4*>(x2f);
    const float4* y2 = reinterpret_cast<const float4*>(y2f);
    float4* o0 = reinterpret_cast<float4*>(o0f);
    float4* o1 = reinterpret_cast<float4*>(o1f);
    float4* o2 = reinterpret_cast<float4*>(o2f);

    if (P0 + 2 * PT <= total) {
        // ================= fast path: two full half-tiles =================
        const int g0 = P0 >> 2;          // f4 index of half 0
        const int g1 = g0 + (PT >> 2);   // f4 index of half 1

        stage_half(sbuf, g0, tid, x0, y0, x1, y1, x2, y2);
        asm volatile("cp.async.commit_group;");
        stage_half(sbuf + BUF_F4, g1, tid, x0, y0, x1, y1, x2, y2);
        asm volatile("cp.async.commit_group;");

        // half 0: compute+store while half 1 still in flight
        asm volatile("cp.async.wait_group 1;");
        __syncthreads();
        compute_half(sbuf, tid);
        __syncthreads();
        store_half(sbuf, g0, tid, o0, o1, o2);

        // half 1
        asm volatile("cp.async.wait_group 0;");
        __syncthreads();
        compute_half(sbuf + BUF_F4, tid);
        __syncthreads();
        store_half(sbuf + BUF_F4, g1, tid, o0, o1, o2);
    } else {
        // ================= tail path: scalar with guards =================
        for (int h = 0; h < 2; ++h) {
            int p = P0 + h * PT + tid;
            if (tid < PT && p < total) {
                float a = x0f[p], b = y0f[p];
                float u[3], v[3], A[9], B[9];
#pragma unroll
                for (int i = 0; i < 3; ++i) { u[i] = x1f[p * 3 + i]; v[i] = y1f[p * 3 + i]; }
#pragma unroll
                for (int i = 0; i < 9; ++i) { A[i] = x2f[p * 9 + i]; B[i] = y2f[p * 9 + i]; }
                float r0, r1[3], r2[9];
                tp_pair(a, b, u, v, A, B, &r0, r1, r2);
                o0f[p] = r0;
#pragma unroll
                for (int i = 0; i < 3; ++i) o1f[p * 3 + i] = r1[i];
#pragma unroll
                for (int i = 0; i < 9; ++i) o2f[p * 9 + i] = r2[i];
            }
        }
    }
}

extern "C" void kernel_launch(void* const* d_in, const int* in_sizes, int n_in,
                              void* d_out, int out_size)
{
    // Resolve inputs by element count: s = base (rank-0), 3s (rank-1), 9s (rank-2).
    // First occurrence of a size = x tensor, second = y tensor (robust to both
    // metadata orderings).
    int s = in_sizes[0];
    for (int i = 1; i < n_in; ++i) if (in_sizes[i] < s) s = in_sizes[i];

    const float* X[3] = {nullptr, nullptr, nullptr};
    const float* Y[3] = {nullptr, nullptr, nullptr};
    for (int i = 0; i < n_in; ++i) {
        int r;
        if (in_sizes[i] == s)          r = 0;
        else if (in_sizes[i] == 3 * s) r = 1;
        else                           r = 2;
        if (X[r] == nullptr) X[r] = (const float*)d_in[i];
        else                 Y[r] = (const float*)d_in[i];
    }

    float* o0 = (float*)d_out;       // s elements
    float* o1 = o0 + (size_t)s;      // 3s elements
    float* o2 = o0 + (size_t)4 * s;  // 9s elements

    int blocks = (s + 2 * PT - 1) / (2 * PT);
    tp_kernel_split<<<blocks, TPB>>>(X[0], Y[0], X[1], Y[1], X[2], Y[2],
                                     o0, o1, o2, s);
}